// round 6
// baseline (speedup 1.0000x reference)
#include <cuda_runtime.h>

// Fused DepthwiseSeparableConv3d: depthwise 3x3x3 (SAME) + bias + BN + ReLU,
// then pointwise 64->128 GEMM + bias + BN + ReLU.
// B=2, D=H=W=48, C=64, F=128. fp32, f32x2 GEMM.
// R6 = R1 structure with a mov-free GEMM inner loop:
//   - y stored PRE-DUPLICATED in smem as u64 (z,z) pairs -> broadcast LDS.128
//     feeds fma2 directly (no dup2 in the 64-iter loop).
//   - weights read as native f-pair u64 via __ldg (L1-resident 32KB set),
//     removing per-block smem staging entirely.

#define NB   2
#define ND   48
#define NC   64
#define NF   128
#define YDS  50   // yd row stride in u64 dup-pairs (400B: aligned, low conflict)

__device__ __forceinline__ unsigned long long dup2(float v) {
    unsigned long long r;
    unsigned u = __float_as_uint(v);
    asm("mov.b64 %0, {%1, %1};" : "=l"(r) : "r"(u));
    return r;
}

__device__ __forceinline__ void fma2(unsigned long long& d,
                                     unsigned long long a,
                                     unsigned long long b) {
    asm("fma.rn.f32x2 %0, %1, %2, %0;" : "+l"(d) : "l"(a), "l"(b));
}

__device__ __forceinline__ float lo32(unsigned long long v) {
    return __uint_as_float((unsigned)(v & 0xffffffffull));
}
__device__ __forceinline__ float hi32(unsigned long long v) {
    return __uint_as_float((unsigned)(v >> 32));
}

__global__ __launch_bounds__(256, 3)
void dwsep3d_fused_kernel(
    const float* __restrict__ x,
    const float* __restrict__ dwk,   // (3,3,3,1,C)
    const float* __restrict__ dwb,   // (C)
    const float* __restrict__ g1, const float* __restrict__ b1,
    const float* __restrict__ m1, const float* __restrict__ v1,
    const float* __restrict__ pw,    // (C,F)
    const float* __restrict__ pb,    // (F)
    const float* __restrict__ g2, const float* __restrict__ b2,
    const float* __restrict__ m2, const float* __restrict__ v2,
    float* __restrict__ out)
{
    __shared__ unsigned long long yd[NC * YDS];   // 25600 B, y dup-pairs [c][w]
    __shared__ float sS1[NC], sT1[NC];
    __shared__ float sS2[NF], sT2[NF];

    const int tid = threadIdx.x;
    const int bid = blockIdx.x;            // 0 .. B*D*H-1
    const int h = bid % ND;
    const int d = (bid / ND) % ND;
    const int b = bid / (ND * ND);

    // ---- stage 0: fold BN params --------------------------------------------
    if (tid < NC) {
        const int c = tid;
        float inv = g1[c] * rsqrtf(v1[c] + 1e-3f);
        sS1[c] = inv;
        sT1[c] = dwb[c] * inv + b1[c] - m1[c] * inv;   // folds dw bias + BN1
    } else if (tid < NC + NF) {
        const int f = tid - NC;
        float inv = g2[f] * rsqrtf(v2[f] + 1e-3f);
        sS2[f] = inv;
        sT2[f] = pb[f] * inv + b2[f] - m2[f] * inv;    // folds pw bias + BN2
    }
    __syncthreads();

    // ---- stage 1: depthwise 3x3x3 + BN1 + ReLU -> yd[c][w] dup-pairs ---------
    {
        const int c  = tid & 63;           // channel
        const int wg = tid >> 6;           // 0..3 -> w range [wg*12, wg*12+12)
        const int w0 = wg * 12;

        float acc[12];
        #pragma unroll
        for (int j = 0; j < 12; j++) acc[j] = 0.f;

        #pragma unroll
        for (int dd = 0; dd < 3; dd++) {
            const int zd = d + dd - 1;
            if (zd < 0 || zd >= ND) continue;
            #pragma unroll
            for (int hh = 0; hh < 3; hh++) {
                const int zh = h + hh - 1;
                if (zh < 0 || zh >= ND) continue;
                const float* xb =
                    x + (((size_t)((b * ND + zd) * ND + zh)) * ND) * NC + c;
                float xv[14];
                #pragma unroll
                for (int j = 0; j < 14; j++) {
                    const int wx = w0 - 1 + j;
                    xv[j] = (wx >= 0 && wx < ND) ? __ldg(xb + wx * NC) : 0.f;
                }
                const int kb = ((dd * 3 + hh) * 3) * NC + c;
                const float k0 = __ldg(dwk + kb);
                const float k1 = __ldg(dwk + kb + NC);
                const float k2 = __ldg(dwk + kb + 2 * NC);
                #pragma unroll
                for (int j = 0; j < 12; j++)
                    acc[j] = fmaf(xv[j], k0,
                              fmaf(xv[j + 1], k1,
                               fmaf(xv[j + 2], k2, acc[j])));
            }
        }
        const float s1v = sS1[c], t1v = sT1[c];
        unsigned long long* yr = &yd[c * YDS + w0];
        #pragma unroll
        for (int j = 0; j < 12; j++) {
            const float z = fmaxf(fmaf(acc[j], s1v, t1v), 0.f);
            yr[j] = dup2(z);               // duplicated pair (z, z)
        }
    }
    __syncthreads();

    // ---- stage 2: GEMM z[48][128] = y[48][64] @ W[64][128] -------------------
    // warp: 6 w (uniform, 3 broadcast LDS.128 of dup-pairs);
    // lane: 4 f = 2 native f-pairs via __ldg ulonglong2. Zero movs in loop.
    {
        const int lane = tid & 31;
        const int wid  = tid >> 5;         // 0..7
        const int f0   = lane * 4;
        const int w0   = wid * 6;

        unsigned long long acc[6][2];      // [w][f-pair]
        #pragma unroll
        for (int p = 0; p < 6; p++) {
            acc[p][0] = 0ull; acc[p][1] = 0ull;
        }

        const ulonglong2* wvp = (const ulonglong2*)(pw + f0);
        const unsigned long long* yb = &yd[w0];

        #pragma unroll 4
        for (int c = 0; c < NC; c++) {
            const ulonglong2 wv = __ldg(wvp + c * (NF / 4));
            const ulonglong2 ya = *(const ulonglong2*)(yb + c * YDS);
            const ulonglong2 yc = *(const ulonglong2*)(yb + c * YDS + 2);
            const ulonglong2 ye = *(const ulonglong2*)(yb + c * YDS + 4);

            fma2(acc[0][0], ya.x, wv.x); fma2(acc[0][1], ya.x, wv.y);
            fma2(acc[1][0], ya.y, wv.x); fma2(acc[1][1], ya.y, wv.y);
            fma2(acc[2][0], yc.x, wv.x); fma2(acc[2][1], yc.x, wv.y);
            fma2(acc[3][0], yc.y, wv.x); fma2(acc[3][1], yc.y, wv.y);
            fma2(acc[4][0], ye.x, wv.x); fma2(acc[4][1], ye.x, wv.y);
            fma2(acc[5][0], ye.y, wv.x); fma2(acc[5][1], ye.y, wv.y);
        }

        // epilogue: BN2 + ReLU; per w the warp writes 512B contiguous.
        const float4 s2 = *(const float4*)&sS2[f0];
        const float4 t2 = *(const float4*)&sT2[f0];
        float* ob = out + (((size_t)((b * ND + d) * ND + h)) * ND + w0) * NF + f0;

        #pragma unroll
        for (int p = 0; p < 6; p++) {
            float4 o;
            o.x = fmaxf(fmaf(lo32(acc[p][0]), s2.x, t2.x), 0.f);
            o.y = fmaxf(fmaf(hi32(acc[p][0]), s2.y, t2.y), 0.f);
            o.z = fmaxf(fmaf(lo32(acc[p][1]), s2.z, t2.z), 0.f);
            o.w = fmaxf(fmaf(hi32(acc[p][1]), s2.w, t2.w), 0.f);
            *(float4*)&ob[(size_t)p * NF] = o;
        }
    }
}

extern "C" void kernel_launch(void* const* d_in, const int* in_sizes, int n_in,
                              void* d_out, int out_size) {
    const float* x   = (const float*)d_in[0];
    const float* dwk = (const float*)d_in[1];
    const float* dwb = (const float*)d_in[2];
    const float* g1  = (const float*)d_in[3];
    const float* b1  = (const float*)d_in[4];
    const float* m1  = (const float*)d_in[5];
    const float* v1  = (const float*)d_in[6];
    const float* pw  = (const float*)d_in[7];
    const float* pb  = (const float*)d_in[8];
    const float* g2  = (const float*)d_in[9];
    const float* b2  = (const float*)d_in[10];
    const float* m2  = (const float*)d_in[11];
    const float* v2  = (const float*)d_in[12];
    float* out = (float*)d_out;

    dim3 grid(NB * ND * ND);   // 4608 blocks: one (b,d,h) row (48 w) each
    dim3 block(256);
    dwsep3d_fused_kernel<<<grid, block>>>(x, dwk, dwb, g1, b1, m1, v1,
                                          pw, pb, g2, b2, m2, v2, out);
}

// round 9
// speedup vs baseline: 1.3087x; 1.3087x over previous
#include <cuda_runtime.h>
#include <cuda_bf16.h>
#include <cstdint>

// Fused DepthwiseSeparableConv3d: depthwise 3x3x3 (SAME) + bias + BN + ReLU,
// then pointwise 64->128 GEMM + bias + BN + ReLU.
// B=2, D=H=W=48, C=64, F=128.
// R9 = R8 with the epilogue addressing bug fixed (hr*ND, not hr*ND*ND).
// Pointwise GEMM on the tensor pipe via warp-level mma.sync (bf16, m16n8k16,
// fp32 accum). Precision: bf16 hi/lo split, 3 passes (hi*hi + hi*lo + lo*hi),
// err ~2^-17. Block = (b, d, h-pair): M=96 = 6 m16-tiles, N=128, K=64.

#define NB   2
#define ND   48
#define NC   64    // K
#define NF   128   // N
#define SW   144   // row stride in bytes for bf16 tiles (72 elems): banks 4g+tg

// dynamic smem layout (bytes)
#define OFF_S1   0           // 64 floats
#define OFF_T1   256
#define OFF_S2   512         // 128 floats
#define OFF_T2   1024
#define OFF_YHI  1536        // 96 rows x 144B
#define OFF_YLO  (OFF_YHI + 96 * SW)      // 15360
#define OFF_WHI  (OFF_YLO + 96 * SW)      // 29184, 128 rows x 144B
#define OFF_WLO  (OFF_WHI + 128 * SW)     // 47616
#define SM_TOTAL (OFF_WLO + 128 * SW)     // 66048

__device__ __forceinline__ void mma_bf16(float* d, const uint32_t* a,
                                         const uint32_t* b) {
    asm volatile(
        "mma.sync.aligned.m16n8k16.row.col.f32.bf16.bf16.f32 "
        "{%0,%1,%2,%3}, {%4,%5,%6,%7}, {%8,%9}, {%0,%1,%2,%3};\n"
        : "+f"(d[0]), "+f"(d[1]), "+f"(d[2]), "+f"(d[3])
        : "r"(a[0]), "r"(a[1]), "r"(a[2]), "r"(a[3]), "r"(b[0]), "r"(b[1]));
}

__global__ __launch_bounds__(256, 2)
void dwsep3d_mma_kernel(
    const float* __restrict__ x,
    const float* __restrict__ dwk,   // (3,3,3,1,C)
    const float* __restrict__ dwb,
    const float* __restrict__ g1, const float* __restrict__ b1,
    const float* __restrict__ m1, const float* __restrict__ v1,
    const float* __restrict__ pw,    // (C,F)
    const float* __restrict__ pb,
    const float* __restrict__ g2, const float* __restrict__ b2,
    const float* __restrict__ m2, const float* __restrict__ v2,
    float* __restrict__ out)
{
    extern __shared__ char smem[];
    float* sS1 = (float*)(smem + OFF_S1);
    float* sT1 = (float*)(smem + OFF_T1);
    float* sS2 = (float*)(smem + OFF_S2);
    float* sT2 = (float*)(smem + OFF_T2);

    const int tid = threadIdx.x;
    const int bid = blockIdx.x;            // 0 .. NB*ND*24-1
    const int h0 = (bid % 24) * 2;
    const int d  = (bid / 24) % ND;
    const int b  = bid / (24 * ND);

    // ---- fold BN params -----------------------------------------------------
    if (tid < NC) {
        const int c = tid;
        float inv = g1[c] * rsqrtf(v1[c] + 1e-3f);
        sS1[c] = inv;
        sT1[c] = dwb[c] * inv + b1[c] - m1[c] * inv;   // folds dw bias + BN1
    } else if (tid < NC + NF) {
        const int f = tid - NC;
        float inv = g2[f] * rsqrtf(v2[f] + 1e-3f);
        sS2[f] = inv;
        sT2[f] = pb[f] * inv + b2[f] - m2[f] * inv;    // folds pw bias + BN2
    }

    // ---- stage weights transposed: wT[f][c] = bf16 hi/lo of pw[c][f] --------
    for (int i = tid; i < NC * NF; i += 256) {
        const int c = i >> 7;
        const int f = i & 127;
        const float w = __ldg(pw + i);
        const __nv_bfloat16 whi = __float2bfloat16(w);
        const __nv_bfloat16 wlo = __float2bfloat16(w - __bfloat162float(whi));
        *(__nv_bfloat16*)(smem + OFF_WHI + f * SW + c * 2) = whi;
        *(__nv_bfloat16*)(smem + OFF_WLO + f * SW + c * 2) = wlo;
    }
    __syncthreads();

    // ---- stage 1: depthwise 3x3x3 + BN1 + ReLU -> yHi/yLo[m][c] bf16 --------
    {
        const int c  = tid & 63;           // channel
        const int wg = tid >> 6;           // 0..3 -> 12 w each
        const int w0 = wg * 12;
        const float s1v = sS1[c], t1v = sT1[c];

        #pragma unroll
        for (int hr = 0; hr < 2; hr++) {
            const int h = h0 + hr;
            float acc[12];
            #pragma unroll
            for (int j = 0; j < 12; j++) acc[j] = 0.f;

            #pragma unroll
            for (int dd = 0; dd < 3; dd++) {
                const int zd = d + dd - 1;
                if (zd < 0 || zd >= ND) continue;
                #pragma unroll
                for (int hh = 0; hh < 3; hh++) {
                    const int zh = h + hh - 1;
                    if (zh < 0 || zh >= ND) continue;
                    const float* xb =
                        x + (((size_t)((b * ND + zd) * ND + zh)) * ND) * NC + c;
                    float xv[14];
                    #pragma unroll
                    for (int j = 0; j < 14; j++) {
                        const int wx = w0 - 1 + j;
                        xv[j] = (wx >= 0 && wx < ND) ? __ldg(xb + wx * NC) : 0.f;
                    }
                    const int kb = ((dd * 3 + hh) * 3) * NC + c;
                    const float k0 = __ldg(dwk + kb);
                    const float k1 = __ldg(dwk + kb + NC);
                    const float k2 = __ldg(dwk + kb + 2 * NC);
                    #pragma unroll
                    for (int j = 0; j < 12; j++)
                        acc[j] = fmaf(xv[j], k0,
                                  fmaf(xv[j + 1], k1,
                                   fmaf(xv[j + 2], k2, acc[j])));
                }
            }
            #pragma unroll
            for (int j = 0; j < 12; j++) {
                const float z = fmaxf(fmaf(acc[j], s1v, t1v), 0.f);
                const __nv_bfloat16 zhi = __float2bfloat16(z);
                const __nv_bfloat16 zlo =
                    __float2bfloat16(z - __bfloat162float(zhi));
                const int m = hr * 48 + w0 + j;
                *(__nv_bfloat16*)(smem + OFF_YHI + m * SW + c * 2) = zhi;
                *(__nv_bfloat16*)(smem + OFF_YLO + m * SW + c * 2) = zlo;
            }
        }
    }
    __syncthreads();

    // ---- stage 2: GEMM on tensor pipe: D[96][128] = y[96][64] @ W^T ---------
    // warp w owns n16 = [w*16, w*16+16); all 6 m16-tiles; 3-pass hi/lo.
    {
        const int lane = tid & 31;
        const int wid  = tid >> 5;         // 0..7
        const int g    = lane >> 2;        // group id (rows / cols)
        const int tg   = lane & 3;         // thread-in-group
        const int n0   = wid * 16;

        float acc[6][2][4];
        #pragma unroll
        for (int mt = 0; mt < 6; mt++)
            #pragma unroll
            for (int nt = 0; nt < 2; nt++)
                #pragma unroll
                for (int q = 0; q < 4; q++) acc[mt][nt][q] = 0.f;

        #pragma unroll
        for (int ks = 0; ks < 4; ks++) {
            const int kb = ks * 32 + tg * 4;   // byte offset within a row

            uint32_t bh[2][2], bl[2][2];
            #pragma unroll
            for (int nt = 0; nt < 2; nt++) {
                const int nrow = n0 + nt * 8 + g;
                const char* ph = smem + OFF_WHI + nrow * SW + kb;
                const char* pl = smem + OFF_WLO + nrow * SW + kb;
                bh[nt][0] = *(const uint32_t*)ph;
                bh[nt][1] = *(const uint32_t*)(ph + 16);
                bl[nt][0] = *(const uint32_t*)pl;
                bl[nt][1] = *(const uint32_t*)(pl + 16);
            }

            #pragma unroll
            for (int mt = 0; mt < 6; mt++) {
                const int mrow = mt * 16 + g;
                const char* ph = smem + OFF_YHI + mrow * SW + kb;
                const char* pl = smem + OFF_YLO + mrow * SW + kb;
                uint32_t ah[4], al[4];
                ah[0] = *(const uint32_t*)ph;
                ah[1] = *(const uint32_t*)(ph + 8 * SW);
                ah[2] = *(const uint32_t*)(ph + 16);
                ah[3] = *(const uint32_t*)(ph + 8 * SW + 16);
                al[0] = *(const uint32_t*)pl;
                al[1] = *(const uint32_t*)(pl + 8 * SW);
                al[2] = *(const uint32_t*)(pl + 16);
                al[3] = *(const uint32_t*)(pl + 8 * SW + 16);

                #pragma unroll
                for (int nt = 0; nt < 2; nt++) {
                    mma_bf16(acc[mt][nt], ah, bh[nt]);
                    mma_bf16(acc[mt][nt], ah, bl[nt]);
                    mma_bf16(acc[mt][nt], al, bh[nt]);
                }
            }
        }

        // ---- epilogue: BN2 + ReLU, direct float2 stores ---------------------
        // out row (h0+hr, w) lives at ((base + h0+hr)*ND + w)*NF:
        // offset from ob = (hr*ND + w)*NF.   (R8 bug: had hr*ND*ND)
        float* ob = out + (((size_t)((b * ND + d) * ND + h0)) * ND) * NF;
        #pragma unroll
        for (int nt = 0; nt < 2; nt++) {
            const int f0 = n0 + nt * 8 + tg * 2;
            const float2 s2 = *(const float2*)&sS2[f0];
            const float2 t2 = *(const float2*)&sT2[f0];
            #pragma unroll
            for (int mt = 0; mt < 6; mt++) {
                #pragma unroll
                for (int half = 0; half < 2; half++) {
                    const int m = mt * 16 + g + half * 8;
                    const int hr = (m >= 48) ? 1 : 0;
                    const int w  = m - hr * 48;
                    float2 o;
                    o.x = fmaxf(fmaf(acc[mt][nt][half * 2],     s2.x, t2.x), 0.f);
                    o.y = fmaxf(fmaf(acc[mt][nt][half * 2 + 1], s2.y, t2.y), 0.f);
                    *(float2*)&ob[((size_t)hr * ND + w) * NF + f0] = o;
                }
            }
        }
    }
}

extern "C" void kernel_launch(void* const* d_in, const int* in_sizes, int n_in,
                              void* d_out, int out_size) {
    const float* x   = (const float*)d_in[0];
    const float* dwk = (const float*)d_in[1];
    const float* dwb = (const float*)d_in[2];
    const float* g1  = (const float*)d_in[3];
    const float* b1  = (const float*)d_in[4];
    const float* m1  = (const float*)d_in[5];
    const float* v1  = (const float*)d_in[6];
    const float* pw  = (const float*)d_in[7];
    const float* pb  = (const float*)d_in[8];
    const float* g2  = (const float*)d_in[9];
    const float* b2  = (const float*)d_in[10];
    const float* m2  = (const float*)d_in[11];
    const float* v2  = (const float*)d_in[12];
    float* out = (float*)d_out;

    static int smem_set = 0;
    if (!smem_set) {
        cudaFuncSetAttribute(dwsep3d_mma_kernel,
                             cudaFuncAttributeMaxDynamicSharedMemorySize,
                             SM_TOTAL);
        smem_set = 1;
    }

    dim3 grid(NB * ND * 24);   // 2304 blocks: one (b,d,h-pair) -> 96 voxels
    dim3 block(256);
    dwsep3d_mma_kernel<<<grid, block, SM_TOTAL>>>(x, dwk, dwb, g1, b1, m1, v1,
                                                  pw, pb, g2, b2, m2, v2, out);
}

// round 10
// speedup vs baseline: 1.4239x; 1.0880x over previous
#include <cuda_runtime.h>
#include <cuda_bf16.h>
#include <cstdint>

// Fused DepthwiseSeparableConv3d: depthwise 3x3x3 (SAME) + bias + BN + ReLU,
// then pointwise 64->128 GEMM + bias + BN + ReLU.
// B=2, D=H=W=48, C=64, F=128.
// R10 = R9 (tensor-pipe mma.sync GEMM, bf16 hi/lo 3-pass) with stage-1
// rewritten over channel PAIRS: float2 LDG (half the loads), float2-component
// FFMA (no packing movs), and paired-bf16 u32 STS (half the stores).

#define NB   2
#define ND   48
#define NC   64    // K
#define NF   128   // N
#define SW   144   // row stride in bytes for bf16 tiles (72 elems)

// dynamic smem layout (bytes)
#define OFF_S1   0           // 64 floats
#define OFF_T1   256
#define OFF_S2   512         // 128 floats
#define OFF_T2   1024
#define OFF_YHI  1536        // 96 rows x 144B
#define OFF_YLO  (OFF_YHI + 96 * SW)      // 15360
#define OFF_WHI  (OFF_YLO + 96 * SW)      // 29184, 128 rows x 144B
#define OFF_WLO  (OFF_WHI + 128 * SW)     // 47616
#define SM_TOTAL (OFF_WLO + 128 * SW)     // 66048

__device__ __forceinline__ void mma_bf16(float* d, const uint32_t* a,
                                         const uint32_t* b) {
    asm volatile(
        "mma.sync.aligned.m16n8k16.row.col.f32.bf16.bf16.f32 "
        "{%0,%1,%2,%3}, {%4,%5,%6,%7}, {%8,%9}, {%0,%1,%2,%3};\n"
        : "+f"(d[0]), "+f"(d[1]), "+f"(d[2]), "+f"(d[3])
        : "r"(a[0]), "r"(a[1]), "r"(a[2]), "r"(a[3]), "r"(b[0]), "r"(b[1]));
}

__device__ __forceinline__ uint32_t bf16pair(float a, float b) {
    __nv_bfloat162 p = __floats2bfloat162_rn(a, b);
    return *(uint32_t*)&p;
}

__global__ __launch_bounds__(256, 2)
void dwsep3d_mma_kernel(
    const float* __restrict__ x,
    const float* __restrict__ dwk,   // (3,3,3,1,C)
    const float* __restrict__ dwb,
    const float* __restrict__ g1, const float* __restrict__ b1,
    const float* __restrict__ m1, const float* __restrict__ v1,
    const float* __restrict__ pw,    // (C,F)
    const float* __restrict__ pb,
    const float* __restrict__ g2, const float* __restrict__ b2,
    const float* __restrict__ m2, const float* __restrict__ v2,
    float* __restrict__ out)
{
    extern __shared__ char smem[];
    float* sS1 = (float*)(smem + OFF_S1);
    float* sT1 = (float*)(smem + OFF_T1);
    float* sS2 = (float*)(smem + OFF_S2);
    float* sT2 = (float*)(smem + OFF_T2);

    const int tid = threadIdx.x;
    const int bid = blockIdx.x;            // 0 .. NB*ND*24-1
    const int h0 = (bid % 24) * 2;
    const int d  = (bid / 24) % ND;
    const int b  = bid / (24 * ND);

    // ---- fold BN params -----------------------------------------------------
    if (tid < NC) {
        const int c = tid;
        float inv = g1[c] * rsqrtf(v1[c] + 1e-3f);
        sS1[c] = inv;
        sT1[c] = dwb[c] * inv + b1[c] - m1[c] * inv;   // folds dw bias + BN1
    } else if (tid < NC + NF) {
        const int f = tid - NC;
        float inv = g2[f] * rsqrtf(v2[f] + 1e-3f);
        sS2[f] = inv;
        sT2[f] = pb[f] * inv + b2[f] - m2[f] * inv;    // folds pw bias + BN2
    }

    // ---- stage weights transposed: wT[f][c-pair] u32 of bf16 hi/lo ----------
    // thread i handles (c-pair, f): 32 c-pairs x 128 f / 256 threads = 16 iters
    for (int i = tid; i < (NC / 2) * NF; i += 256) {
        const int cp = i >> 7;             // 0..31
        const int f  = i & 127;
        const float w0v = __ldg(pw + (2 * cp) * NF + f);
        const float w1v = __ldg(pw + (2 * cp + 1) * NF + f);
        const __nv_bfloat16 h0v = __float2bfloat16(w0v);
        const __nv_bfloat16 h1v = __float2bfloat16(w1v);
        const float l0 = w0v - __bfloat162float(h0v);
        const float l1 = w1v - __bfloat162float(h1v);
        *(uint32_t*)(smem + OFF_WHI + f * SW + cp * 4) =
            ((uint32_t)*(const uint16_t*)&h1v << 16) | *(const uint16_t*)&h0v;
        *(uint32_t*)(smem + OFF_WLO + f * SW + cp * 4) = bf16pair(l0, l1);
    }
    __syncthreads();

    // ---- stage 1: depthwise 3x3x3 + BN1 + ReLU over channel pairs -----------
    // thread = (cp = tid&31 -> channels 2cp,2cp+1 ; seg = tid>>5 -> hr, 12 w)
    {
        const int cp  = tid & 31;
        const int c0  = cp * 2;
        const int seg = tid >> 5;          // 0..7
        const int hr  = seg >> 2;          // 0..1
        const int w0  = (seg & 3) * 12;
        const int h   = h0 + hr;

        float2 acc[12];
        #pragma unroll
        for (int j = 0; j < 12; j++) acc[j] = make_float2(0.f, 0.f);

        #pragma unroll
        for (int dd = 0; dd < 3; dd++) {
            const int zd = d + dd - 1;
            if (zd < 0 || zd >= ND) continue;
            #pragma unroll
            for (int hh = 0; hh < 3; hh++) {
                const int zh = h + hh - 1;
                if (zh < 0 || zh >= ND) continue;
                const float* xb =
                    x + (((size_t)((b * ND + zd) * ND + zh)) * ND) * NC + c0;
                float2 xv[14];
                #pragma unroll
                for (int j = 0; j < 14; j++) {
                    const int wx = w0 - 1 + j;
                    xv[j] = (wx >= 0 && wx < ND)
                        ? __ldg((const float2*)(xb + wx * NC))
                        : make_float2(0.f, 0.f);
                }
                const float* kb = dwk + ((dd * 3 + hh) * 3) * NC + c0;
                const float2 k0 = __ldg((const float2*)kb);
                const float2 k1 = __ldg((const float2*)(kb + NC));
                const float2 k2 = __ldg((const float2*)(kb + 2 * NC));
                #pragma unroll
                for (int j = 0; j < 12; j++) {
                    acc[j].x = fmaf(xv[j].x, k0.x,
                               fmaf(xv[j + 1].x, k1.x,
                                fmaf(xv[j + 2].x, k2.x, acc[j].x)));
                    acc[j].y = fmaf(xv[j].y, k0.y,
                               fmaf(xv[j + 1].y, k1.y,
                                fmaf(xv[j + 2].y, k2.y, acc[j].y)));
                }
            }
        }
        const float2 s1 = *(const float2*)&sS1[c0];
        const float2 t1 = *(const float2*)&sT1[c0];
        #pragma unroll
        for (int j = 0; j < 12; j++) {
            const float z0 = fmaxf(fmaf(acc[j].x, s1.x, t1.x), 0.f);
            const float z1 = fmaxf(fmaf(acc[j].y, s1.y, t1.y), 0.f);
            const __nv_bfloat16 zh0 = __float2bfloat16(z0);
            const __nv_bfloat16 zh1 = __float2bfloat16(z1);
            const float zl0 = z0 - __bfloat162float(zh0);
            const float zl1 = z1 - __bfloat162float(zh1);
            const int m = hr * 48 + w0 + j;
            *(uint32_t*)(smem + OFF_YHI + m * SW + cp * 4) =
                ((uint32_t)*(const uint16_t*)&zh1 << 16) | *(const uint16_t*)&zh0;
            *(uint32_t*)(smem + OFF_YLO + m * SW + cp * 4) = bf16pair(zl0, zl1);
        }
    }
    __syncthreads();

    // ---- stage 2: GEMM on tensor pipe: D[96][128] = y[96][64] @ W^T ---------
    // warp w owns n16 = [w*16, w*16+16); all 6 m16-tiles; 3-pass hi/lo.
    {
        const int lane = tid & 31;
        const int wid  = tid >> 5;         // 0..7
        const int g    = lane >> 2;        // group id (rows / cols)
        const int tg   = lane & 3;         // thread-in-group
        const int n0   = wid * 16;

        float acc[6][2][4];
        #pragma unroll
        for (int mt = 0; mt < 6; mt++)
            #pragma unroll
            for (int nt = 0; nt < 2; nt++)
                #pragma unroll
                for (int q = 0; q < 4; q++) acc[mt][nt][q] = 0.f;

        #pragma unroll
        for (int ks = 0; ks < 4; ks++) {
            const int kb = ks * 32 + tg * 4;   // byte offset within a row

            uint32_t bh[2][2], bl[2][2];
            #pragma unroll
            for (int nt = 0; nt < 2; nt++) {
                const int nrow = n0 + nt * 8 + g;
                const char* ph = smem + OFF_WHI + nrow * SW + kb;
                const char* pl = smem + OFF_WLO + nrow * SW + kb;
                bh[nt][0] = *(const uint32_t*)ph;
                bh[nt][1] = *(const uint32_t*)(ph + 16);
                bl[nt][0] = *(const uint32_t*)pl;
                bl[nt][1] = *(const uint32_t*)(pl + 16);
            }

            #pragma unroll
            for (int mt = 0; mt < 6; mt++) {
                const int mrow = mt * 16 + g;
                const char* ph = smem + OFF_YHI + mrow * SW + kb;
                const char* pl = smem + OFF_YLO + mrow * SW + kb;
                uint32_t ah[4], al[4];
                ah[0] = *(const uint32_t*)ph;
                ah[1] = *(const uint32_t*)(ph + 8 * SW);
                ah[2] = *(const uint32_t*)(ph + 16);
                ah[3] = *(const uint32_t*)(ph + 8 * SW + 16);
                al[0] = *(const uint32_t*)pl;
                al[1] = *(const uint32_t*)(pl + 8 * SW);
                al[2] = *(const uint32_t*)(pl + 16);
                al[3] = *(const uint32_t*)(pl + 8 * SW + 16);

                #pragma unroll
                for (int nt = 0; nt < 2; nt++) {
                    mma_bf16(acc[mt][nt], ah, bh[nt]);
                    mma_bf16(acc[mt][nt], ah, bl[nt]);
                    mma_bf16(acc[mt][nt], al, bh[nt]);
                }
            }
        }

        // ---- epilogue: BN2 + ReLU, direct float2 stores ---------------------
        float* ob = out + (((size_t)((b * ND + d) * ND + h0)) * ND) * NF;
        #pragma unroll
        for (int nt = 0; nt < 2; nt++) {
            const int f0 = n0 + nt * 8 + tg * 2;
            const float2 s2 = *(const float2*)&sS2[f0];
            const float2 t2 = *(const float2*)&sT2[f0];
            #pragma unroll
            for (int mt = 0; mt < 6; mt++) {
                #pragma unroll
                for (int half = 0; half < 2; half++) {
                    const int m = mt * 16 + g + half * 8;
                    const int hr = (m >= 48) ? 1 : 0;
                    const int w  = m - hr * 48;
                    float2 o;
                    o.x = fmaxf(fmaf(acc[mt][nt][half * 2],     s2.x, t2.x), 0.f);
                    o.y = fmaxf(fmaf(acc[mt][nt][half * 2 + 1], s2.y, t2.y), 0.f);
                    *(float2*)&ob[((size_t)hr * ND + w) * NF + f0] = o;
                }
            }
        }
    }
}

extern "C" void kernel_launch(void* const* d_in, const int* in_sizes, int n_in,
                              void* d_out, int out_size) {
    const float* x   = (const float*)d_in[0];
    const float* dwk = (const float*)d_in[1];
    const float* dwb = (const float*)d_in[2];
    const float* g1  = (const float*)d_in[3];
    const float* b1  = (const float*)d_in[4];
    const float* m1  = (const float*)d_in[5];
    const float* v1  = (const float*)d_in[6];
    const float* pw  = (const float*)d_in[7];
    const float* pb  = (const float*)d_in[8];
    const float* g2  = (const float*)d_in[9];
    const float* b2  = (const float*)d_in[10];
    const float* m2  = (const float*)d_in[11];
    const float* v2  = (const float*)d_in[12];
    float* out = (float*)d_out;

    static int smem_set = 0;
    if (!smem_set) {
        cudaFuncSetAttribute(dwsep3d_mma_kernel,
                             cudaFuncAttributeMaxDynamicSharedMemorySize,
                             SM_TOTAL);
        smem_set = 1;
    }

    dim3 grid(NB * ND * 24);   // 2304 blocks: one (b,d,h-pair) -> 96 voxels
    dim3 block(256);
    dwsep3d_mma_kernel<<<grid, block, SM_TOTAL>>>(x, dwk, dwb, g1, b1, m1, v1,
                                                  pw, pb, g2, b2, m2, v2, out);
}

// round 11
// speedup vs baseline: 1.4386x; 1.0104x over previous
#include <cuda_runtime.h>
#include <cuda_bf16.h>
#include <cstdint>

// Fused DepthwiseSeparableConv3d: depthwise 3x3x3 (SAME) + bias + BN + ReLU,
// then pointwise 64->128 GEMM + bias + BN + ReLU.
// B=2, D=H=W=48, C=64, F=128.
// R11 = R10 with the tensor-pipe GEMM split into two m-half passes (3 m16
// tiles each, 24 acc regs instead of 48) + __launch_bounds__(256,3) so each
// SM holds 3 CTAs (24 warps) instead of 2 (16) -- latency-hiding fix.

#define NB   2
#define ND   48
#define NC   64    // K
#define NF   128   // N
#define SW   144   // row stride in bytes for bf16 tiles (72 elems)

// dynamic smem layout (bytes)
#define OFF_S1   0           // 64 floats
#define OFF_T1   256
#define OFF_S2   512         // 128 floats
#define OFF_T2   1024
#define OFF_YHI  1536        // 96 rows x 144B
#define OFF_YLO  (OFF_YHI + 96 * SW)      // 15360
#define OFF_WHI  (OFF_YLO + 96 * SW)      // 29184, 128 rows x 144B
#define OFF_WLO  (OFF_WHI + 128 * SW)     // 47616
#define SM_TOTAL (OFF_WLO + 128 * SW)     // 66048

__device__ __forceinline__ void mma_bf16(float* d, const uint32_t* a,
                                         const uint32_t* b) {
    asm volatile(
        "mma.sync.aligned.m16n8k16.row.col.f32.bf16.bf16.f32 "
        "{%0,%1,%2,%3}, {%4,%5,%6,%7}, {%8,%9}, {%0,%1,%2,%3};\n"
        : "+f"(d[0]), "+f"(d[1]), "+f"(d[2]), "+f"(d[3])
        : "r"(a[0]), "r"(a[1]), "r"(a[2]), "r"(a[3]), "r"(b[0]), "r"(b[1]));
}

__device__ __forceinline__ uint32_t bf16pair(float a, float b) {
    __nv_bfloat162 p = __floats2bfloat162_rn(a, b);
    return *(uint32_t*)&p;
}

__global__ __launch_bounds__(256, 3)
void dwsep3d_mma_kernel(
    const float* __restrict__ x,
    const float* __restrict__ dwk,   // (3,3,3,1,C)
    const float* __restrict__ dwb,
    const float* __restrict__ g1, const float* __restrict__ b1,
    const float* __restrict__ m1, const float* __restrict__ v1,
    const float* __restrict__ pw,    // (C,F)
    const float* __restrict__ pb,
    const float* __restrict__ g2, const float* __restrict__ b2,
    const float* __restrict__ m2, const float* __restrict__ v2,
    float* __restrict__ out)
{
    extern __shared__ char smem[];
    float* sS1 = (float*)(smem + OFF_S1);
    float* sT1 = (float*)(smem + OFF_T1);
    float* sS2 = (float*)(smem + OFF_S2);
    float* sT2 = (float*)(smem + OFF_T2);

    const int tid = threadIdx.x;
    const int bid = blockIdx.x;            // 0 .. NB*ND*24-1
    const int h0 = (bid % 24) * 2;
    const int d  = (bid / 24) % ND;
    const int b  = bid / (24 * ND);

    // ---- fold BN params -----------------------------------------------------
    if (tid < NC) {
        const int c = tid;
        float inv = g1[c] * rsqrtf(v1[c] + 1e-3f);
        sS1[c] = inv;
        sT1[c] = dwb[c] * inv + b1[c] - m1[c] * inv;   // folds dw bias + BN1
    } else if (tid < NC + NF) {
        const int f = tid - NC;
        float inv = g2[f] * rsqrtf(v2[f] + 1e-3f);
        sS2[f] = inv;
        sT2[f] = pb[f] * inv + b2[f] - m2[f] * inv;    // folds pw bias + BN2
    }

    // ---- stage weights transposed: wT[f][c-pair] u32 of bf16 hi/lo ----------
    for (int i = tid; i < (NC / 2) * NF; i += 256) {
        const int cp = i >> 7;             // 0..31
        const int f  = i & 127;
        const float w0v = __ldg(pw + (2 * cp) * NF + f);
        const float w1v = __ldg(pw + (2 * cp + 1) * NF + f);
        const __nv_bfloat16 h0v = __float2bfloat16(w0v);
        const __nv_bfloat16 h1v = __float2bfloat16(w1v);
        const float l0 = w0v - __bfloat162float(h0v);
        const float l1 = w1v - __bfloat162float(h1v);
        *(uint32_t*)(smem + OFF_WHI + f * SW + cp * 4) =
            ((uint32_t)*(const uint16_t*)&h1v << 16) | *(const uint16_t*)&h0v;
        *(uint32_t*)(smem + OFF_WLO + f * SW + cp * 4) = bf16pair(l0, l1);
    }
    __syncthreads();

    // ---- stage 1: depthwise 3x3x3 + BN1 + ReLU over channel pairs -----------
    // thread = (cp = tid&31 -> channels 2cp,2cp+1 ; seg = tid>>5 -> hr, 12 w)
    {
        const int cp  = tid & 31;
        const int c0  = cp * 2;
        const int seg = tid >> 5;          // 0..7
        const int hr  = seg >> 2;          // 0..1
        const int w0  = (seg & 3) * 12;
        const int h   = h0 + hr;

        float2 acc[12];
        #pragma unroll
        for (int j = 0; j < 12; j++) acc[j] = make_float2(0.f, 0.f);

        #pragma unroll
        for (int dd = 0; dd < 3; dd++) {
            const int zd = d + dd - 1;
            if (zd < 0 || zd >= ND) continue;
            #pragma unroll
            for (int hh = 0; hh < 3; hh++) {
                const int zh = h + hh - 1;
                if (zh < 0 || zh >= ND) continue;
                const float* xb =
                    x + (((size_t)((b * ND + zd) * ND + zh)) * ND) * NC + c0;
                float2 xv[14];
                #pragma unroll
                for (int j = 0; j < 14; j++) {
                    const int wx = w0 - 1 + j;
                    xv[j] = (wx >= 0 && wx < ND)
                        ? __ldg((const float2*)(xb + wx * NC))
                        : make_float2(0.f, 0.f);
                }
                const float* kb = dwk + ((dd * 3 + hh) * 3) * NC + c0;
                const float2 k0 = __ldg((const float2*)kb);
                const float2 k1 = __ldg((const float2*)(kb + NC));
                const float2 k2 = __ldg((const float2*)(kb + 2 * NC));
                #pragma unroll
                for (int j = 0; j < 12; j++) {
                    acc[j].x = fmaf(xv[j].x, k0.x,
                               fmaf(xv[j + 1].x, k1.x,
                                fmaf(xv[j + 2].x, k2.x, acc[j].x)));
                    acc[j].y = fmaf(xv[j].y, k0.y,
                               fmaf(xv[j + 1].y, k1.y,
                                fmaf(xv[j + 2].y, k2.y, acc[j].y)));
                }
            }
        }
        const float2 s1 = *(const float2*)&sS1[c0];
        const float2 t1 = *(const float2*)&sT1[c0];
        #pragma unroll
        for (int j = 0; j < 12; j++) {
            const float z0 = fmaxf(fmaf(acc[j].x, s1.x, t1.x), 0.f);
            const float z1 = fmaxf(fmaf(acc[j].y, s1.y, t1.y), 0.f);
            const __nv_bfloat16 zh0 = __float2bfloat16(z0);
            const __nv_bfloat16 zh1 = __float2bfloat16(z1);
            const float zl0 = z0 - __bfloat162float(zh0);
            const float zl1 = z1 - __bfloat162float(zh1);
            const int m = hr * 48 + w0 + j;
            *(uint32_t*)(smem + OFF_YHI + m * SW + cp * 4) =
                ((uint32_t)*(const uint16_t*)&zh1 << 16) | *(const uint16_t*)&zh0;
            *(uint32_t*)(smem + OFF_YLO + m * SW + cp * 4) = bf16pair(zl0, zl1);
        }
    }
    __syncthreads();

    // ---- stage 2: GEMM on tensor pipe, two m-half passes --------------------
    // warp w owns n16 = [w*16, w*16+16); pass mh covers m-tiles 3mh..3mh+2.
    {
        const int lane = tid & 31;
        const int wid  = tid >> 5;         // 0..7
        const int g    = lane >> 2;        // group id (rows / cols)
        const int tg   = lane & 3;         // thread-in-group
        const int n0   = wid * 16;

        float* ob = out + (((size_t)((b * ND + d) * ND + h0)) * ND) * NF;

        #pragma unroll
        for (int mh = 0; mh < 2; mh++) {
            float acc[3][2][4];
            #pragma unroll
            for (int mt = 0; mt < 3; mt++)
                #pragma unroll
                for (int nt = 0; nt < 2; nt++)
                    #pragma unroll
                    for (int q = 0; q < 4; q++) acc[mt][nt][q] = 0.f;

            #pragma unroll
            for (int ks = 0; ks < 4; ks++) {
                const int kb = ks * 32 + tg * 4;   // byte offset within a row

                uint32_t bh[2][2], bl[2][2];
                #pragma unroll
                for (int nt = 0; nt < 2; nt++) {
                    const int nrow = n0 + nt * 8 + g;
                    const char* ph = smem + OFF_WHI + nrow * SW + kb;
                    const char* pl = smem + OFF_WLO + nrow * SW + kb;
                    bh[nt][0] = *(const uint32_t*)ph;
                    bh[nt][1] = *(const uint32_t*)(ph + 16);
                    bl[nt][0] = *(const uint32_t*)pl;
                    bl[nt][1] = *(const uint32_t*)(pl + 16);
                }

                #pragma unroll
                for (int mt = 0; mt < 3; mt++) {
                    const int mrow = (mh * 3 + mt) * 16 + g;
                    const char* ph = smem + OFF_YHI + mrow * SW + kb;
                    const char* pl = smem + OFF_YLO + mrow * SW + kb;
                    uint32_t ah[4], al[4];
                    ah[0] = *(const uint32_t*)ph;
                    ah[1] = *(const uint32_t*)(ph + 8 * SW);
                    ah[2] = *(const uint32_t*)(ph + 16);
                    ah[3] = *(const uint32_t*)(ph + 8 * SW + 16);
                    al[0] = *(const uint32_t*)pl;
                    al[1] = *(const uint32_t*)(pl + 8 * SW);
                    al[2] = *(const uint32_t*)(pl + 16);
                    al[3] = *(const uint32_t*)(pl + 8 * SW + 16);

                    #pragma unroll
                    for (int nt = 0; nt < 2; nt++) {
                        mma_bf16(acc[mt][nt], ah, bh[nt]);
                        mma_bf16(acc[mt][nt], ah, bl[nt]);
                        mma_bf16(acc[mt][nt], al, bh[nt]);
                    }
                }
            }

            // ---- epilogue for this m-half: BN2 + ReLU, float2 stores --------
            #pragma unroll
            for (int nt = 0; nt < 2; nt++) {
                const int f0 = n0 + nt * 8 + tg * 2;
                const float2 s2 = *(const float2*)&sS2[f0];
                const float2 t2 = *(const float2*)&sT2[f0];
                #pragma unroll
                for (int mt = 0; mt < 3; mt++) {
                    #pragma unroll
                    for (int half = 0; half < 2; half++) {
                        const int m = (mh * 3 + mt) * 16 + g + half * 8;
                        const int hr = (m >= 48) ? 1 : 0;
                        const int w  = m - hr * 48;
                        float2 o;
                        o.x = fmaxf(fmaf(acc[mt][nt][half * 2],     s2.x, t2.x), 0.f);
                        o.y = fmaxf(fmaf(acc[mt][nt][half * 2 + 1], s2.y, t2.y), 0.f);
                        *(float2*)&ob[((size_t)hr * ND + w) * NF + f0] = o;
                    }
                }
            }
        }
    }
}

extern "C" void kernel_launch(void* const* d_in, const int* in_sizes, int n_in,
                              void* d_out, int out_size) {
    const float* x   = (const float*)d_in[0];
    const float* dwk = (const float*)d_in[1];
    const float* dwb = (const float*)d_in[2];
    const float* g1  = (const float*)d_in[3];
    const float* b1  = (const float*)d_in[4];
    const float* m1  = (const float*)d_in[5];
    const float* v1  = (const float*)d_in[6];
    const float* pw  = (const float*)d_in[7];
    const float* pb  = (const float*)d_in[8];
    const float* g2  = (const float*)d_in[9];
    const float* b2  = (const float*)d_in[10];
    const float* m2  = (const float*)d_in[11];
    const float* v2  = (const float*)d_in[12];
    float* out = (float*)d_out;

    static int smem_set = 0;
    if (!smem_set) {
        cudaFuncSetAttribute(dwsep3d_mma_kernel,
                             cudaFuncAttributeMaxDynamicSharedMemorySize,
                             SM_TOTAL);
        smem_set = 1;
    }

    dim3 grid(NB * ND * 24);   // 2304 blocks: one (b,d,h-pair) -> 96 voxels
    dim3 block(256);
    dwsep3d_mma_kernel<<<grid, block, SM_TOTAL>>>(x, dwk, dwb, g1, b1, m1, v1,
                                                  pw, pb, g2, b2, m2, v2, out);
}

// round 12
// speedup vs baseline: 1.4812x; 1.0296x over previous
#include <cuda_runtime.h>
#include <cuda_bf16.h>
#include <cstdint>

// Fused DepthwiseSeparableConv3d: depthwise 3x3x3 (SAME) + bias + BN + ReLU,
// then pointwise 64->128 GEMM + bias + BN + ReLU.
// B=2, D=H=W=48, C=64, F=128.
// R12 = R11 (tensor-pipe mma.sync GEMM, two m-half passes) with stage-1
// de-serialized: BN1 fold computed per-thread (no smem, no first sync),
// boundary predicates removed from the 12 always-in-bounds window loads,
// single __syncthreads before the GEMM.

#define NB   2
#define ND   48
#define NC   64    // K
#define NF   128   // N
#define SW   144   // row stride in bytes for bf16 tiles (72 elems)

// dynamic smem layout (bytes)
#define OFF_S2   0           // 128 floats
#define OFF_T2   512
#define OFF_YHI  1536        // 96 rows x 144B
#define OFF_YLO  (OFF_YHI + 96 * SW)
#define OFF_WHI  (OFF_YLO + 96 * SW)      // 128 rows x 144B
#define OFF_WLO  (OFF_WHI + 128 * SW)
#define SM_TOTAL (OFF_WLO + 128 * SW)     // 66048

__device__ __forceinline__ void mma_bf16(float* d, const uint32_t* a,
                                         const uint32_t* b) {
    asm volatile(
        "mma.sync.aligned.m16n8k16.row.col.f32.bf16.bf16.f32 "
        "{%0,%1,%2,%3}, {%4,%5,%6,%7}, {%8,%9}, {%0,%1,%2,%3};\n"
        : "+f"(d[0]), "+f"(d[1]), "+f"(d[2]), "+f"(d[3])
        : "r"(a[0]), "r"(a[1]), "r"(a[2]), "r"(a[3]), "r"(b[0]), "r"(b[1]));
}

__device__ __forceinline__ uint32_t bf16pair(float a, float b) {
    __nv_bfloat162 p = __floats2bfloat162_rn(a, b);
    return *(uint32_t*)&p;
}

__global__ __launch_bounds__(256, 3)
void dwsep3d_mma_kernel(
    const float* __restrict__ x,
    const float* __restrict__ dwk,   // (3,3,3,1,C)
    const float* __restrict__ dwb,
    const float* __restrict__ g1, const float* __restrict__ b1,
    const float* __restrict__ m1, const float* __restrict__ v1,
    const float* __restrict__ pw,    // (C,F)
    const float* __restrict__ pb,
    const float* __restrict__ g2, const float* __restrict__ b2,
    const float* __restrict__ m2, const float* __restrict__ v2,
    float* __restrict__ out)
{
    extern __shared__ char smem[];
    float* sS2 = (float*)(smem + OFF_S2);
    float* sT2 = (float*)(smem + OFF_T2);

    const int tid = threadIdx.x;
    const int bid = blockIdx.x;            // 0 .. NB*ND*24-1
    const int h0 = (bid % 24) * 2;
    const int d  = (bid / 24) % ND;
    const int b  = bid / (24 * ND);

    // ---- stage weights transposed: wT[f][c-pair] u32 of bf16 hi/lo ----------
    // (issued first so pw LDGs overlap with the x LDG stream below)
    for (int i = tid; i < (NC / 2) * NF; i += 256) {
        const int cp = i >> 7;             // 0..31
        const int f  = i & 127;
        const float w0v = __ldg(pw + (2 * cp) * NF + f);
        const float w1v = __ldg(pw + (2 * cp + 1) * NF + f);
        const __nv_bfloat16 h0v = __float2bfloat16(w0v);
        const __nv_bfloat16 h1v = __float2bfloat16(w1v);
        const float l0 = w0v - __bfloat162float(h0v);
        const float l1 = w1v - __bfloat162float(h1v);
        *(uint32_t*)(smem + OFF_WHI + f * SW + cp * 4) =
            ((uint32_t)*(const uint16_t*)&h1v << 16) | *(const uint16_t*)&h0v;
        *(uint32_t*)(smem + OFF_WLO + f * SW + cp * 4) = bf16pair(l0, l1);
    }

    // ---- fold BN2 params into smem (needed only after the single sync) ------
    if (tid < NF) {
        const int f = tid;
        float inv = g2[f] * rsqrtf(v2[f] + 1e-3f);
        sS2[f] = inv;
        sT2[f] = pb[f] * inv + b2[f] - m2[f] * inv;
    }

    // ---- stage 1: depthwise 3x3x3 + BN1 + ReLU over channel pairs -----------
    // thread = (cp = tid&31 -> channels 2cp,2cp+1 ; seg = tid>>5 -> hr, 12 w)
    // BN1 fold computed locally -> no smem dependency, no sync needed.
    {
        const int cp  = tid & 31;
        const int c0  = cp * 2;
        const int seg = tid >> 5;          // 0..7 (warp-uniform)
        const int hr  = seg >> 2;          // 0..1
        const int w0  = (seg & 3) * 12;
        const int h   = h0 + hr;

        const float i0 = g1[c0]     * rsqrtf(v1[c0]     + 1e-3f);
        const float i1 = g1[c0 + 1] * rsqrtf(v1[c0 + 1] + 1e-3f);
        const float2 s1 = make_float2(i0, i1);
        const float2 t1 = make_float2(
            fmaf(dwb[c0],     i0, b1[c0])     - m1[c0]     * i0,
            fmaf(dwb[c0 + 1], i1, b1[c0 + 1]) - m1[c0 + 1] * i1);

        float2 acc[12];
        #pragma unroll
        for (int j = 0; j < 12; j++) acc[j] = make_float2(0.f, 0.f);

        #pragma unroll
        for (int dd = 0; dd < 3; dd++) {
            const int zd = d + dd - 1;
            if (zd < 0 || zd >= ND) continue;
            #pragma unroll
            for (int hh = 0; hh < 3; hh++) {
                const int zh = h + hh - 1;
                if (zh < 0 || zh >= ND) continue;
                const float* xb =
                    x + (((size_t)((b * ND + zd) * ND + zh)) * ND) * NC + c0;
                float2 xv[14];
                // interior loads: w0-1+j for j=1..12 is always in [0,47]
                #pragma unroll
                for (int j = 1; j < 13; j++)
                    xv[j] = __ldg((const float2*)(xb + (w0 - 1 + j) * NC));
                // edges: warp-uniform predicates (w0 is per-warp constant)
                xv[0]  = (w0 > 0)
                    ? __ldg((const float2*)(xb + (w0 - 1) * NC))
                    : make_float2(0.f, 0.f);
                xv[13] = (w0 < 36)
                    ? __ldg((const float2*)(xb + (w0 + 12) * NC))
                    : make_float2(0.f, 0.f);

                const float* kb = dwk + ((dd * 3 + hh) * 3) * NC + c0;
                const float2 k0 = __ldg((const float2*)kb);
                const float2 k1 = __ldg((const float2*)(kb + NC));
                const float2 k2 = __ldg((const float2*)(kb + 2 * NC));
                #pragma unroll
                for (int j = 0; j < 12; j++) {
                    acc[j].x = fmaf(xv[j].x, k0.x,
                               fmaf(xv[j + 1].x, k1.x,
                                fmaf(xv[j + 2].x, k2.x, acc[j].x)));
                    acc[j].y = fmaf(xv[j].y, k0.y,
                               fmaf(xv[j + 1].y, k1.y,
                                fmaf(xv[j + 2].y, k2.y, acc[j].y)));
                }
            }
        }
        #pragma unroll
        for (int j = 0; j < 12; j++) {
            const float z0 = fmaxf(fmaf(acc[j].x, s1.x, t1.x), 0.f);
            const float z1 = fmaxf(fmaf(acc[j].y, s1.y, t1.y), 0.f);
            const __nv_bfloat16 zh0 = __float2bfloat16(z0);
            const __nv_bfloat16 zh1 = __float2bfloat16(z1);
            const float zl0 = z0 - __bfloat162float(zh0);
            const float zl1 = z1 - __bfloat162float(zh1);
            const int m = hr * 48 + w0 + j;
            *(uint32_t*)(smem + OFF_YHI + m * SW + cp * 4) =
                ((uint32_t)*(const uint16_t*)&zh1 << 16) | *(const uint16_t*)&zh0;
            *(uint32_t*)(smem + OFF_YLO + m * SW + cp * 4) = bf16pair(zl0, zl1);
        }
    }
    __syncthreads();   // the ONLY sync: y, weights, BN2 params all ready

    // ---- stage 2: GEMM on tensor pipe, two m-half passes --------------------
    // warp w owns n16 = [w*16, w*16+16); pass mh covers m-tiles 3mh..3mh+2.
    {
        const int lane = tid & 31;
        const int wid  = tid >> 5;         // 0..7
        const int g    = lane >> 2;        // group id (rows / cols)
        const int tg   = lane & 3;         // thread-in-group
        const int n0   = wid * 16;

        float* ob = out + (((size_t)((b * ND + d) * ND + h0)) * ND) * NF;

        #pragma unroll
        for (int mh = 0; mh < 2; mh++) {
            float acc[3][2][4];
            #pragma unroll
            for (int mt = 0; mt < 3; mt++)
                #pragma unroll
                for (int nt = 0; nt < 2; nt++)
                    #pragma unroll
                    for (int q = 0; q < 4; q++) acc[mt][nt][q] = 0.f;

            #pragma unroll
            for (int ks = 0; ks < 4; ks++) {
                const int kb = ks * 32 + tg * 4;   // byte offset within a row

                uint32_t bh[2][2], bl[2][2];
                #pragma unroll
                for (int nt = 0; nt < 2; nt++) {
                    const int nrow = n0 + nt * 8 + g;
                    const char* ph = smem + OFF_WHI + nrow * SW + kb;
                    const char* pl = smem + OFF_WLO + nrow * SW + kb;
                    bh[nt][0] = *(const uint32_t*)ph;
                    bh[nt][1] = *(const uint32_t*)(ph + 16);
                    bl[nt][0] = *(const uint32_t*)pl;
                    bl[nt][1] = *(const uint32_t*)(pl + 16);
                }

                #pragma unroll
                for (int mt = 0; mt < 3; mt++) {
                    const int mrow = (mh * 3 + mt) * 16 + g;
                    const char* ph = smem + OFF_YHI + mrow * SW + kb;
                    const char* pl = smem + OFF_YLO + mrow * SW + kb;
                    uint32_t ah[4], al[4];
                    ah[0] = *(const uint32_t*)ph;
                    ah[1] = *(const uint32_t*)(ph + 8 * SW);
                    ah[2] = *(const uint32_t*)(ph + 16);
                    ah[3] = *(const uint32_t*)(ph + 8 * SW + 16);
                    al[0] = *(const uint32_t*)pl;
                    al[1] = *(const uint32_t*)(pl + 8 * SW);
                    al[2] = *(const uint32_t*)(pl + 16);
                    al[3] = *(const uint32_t*)(pl + 8 * SW + 16);

                    #pragma unroll
                    for (int nt = 0; nt < 2; nt++) {
                        mma_bf16(acc[mt][nt], ah, bh[nt]);
                        mma_bf16(acc[mt][nt], ah, bl[nt]);
                        mma_bf16(acc[mt][nt], al, bh[nt]);
                    }
                }
            }

            // ---- epilogue for this m-half: BN2 + ReLU, float2 stores --------
            #pragma unroll
            for (int nt = 0; nt < 2; nt++) {
                const int f0 = n0 + nt * 8 + tg * 2;
                const float2 s2 = *(const float2*)&sS2[f0];
                const float2 t2 = *(const float2*)&sT2[f0];
                #pragma unroll
                for (int mt = 0; mt < 3; mt++) {
                    #pragma unroll
                    for (int half = 0; half < 2; half++) {
                        const int m = (mh * 3 + mt) * 16 + g + half * 8;
                        const int hr = (m >= 48) ? 1 : 0;
                        const int w  = m - hr * 48;
                        float2 o;
                        o.x = fmaxf(fmaf(acc[mt][nt][half * 2],     s2.x, t2.x), 0.f);
                        o.y = fmaxf(fmaf(acc[mt][nt][half * 2 + 1], s2.y, t2.y), 0.f);
                        *(float2*)&ob[((size_t)hr * ND + w) * NF + f0] = o;
                    }
                }
            }
        }
    }
}

extern "C" void kernel_launch(void* const* d_in, const int* in_sizes, int n_in,
                              void* d_out, int out_size) {
    const float* x   = (const float*)d_in[0];
    const float* dwk = (const float*)d_in[1];
    const float* dwb = (const float*)d_in[2];
    const float* g1  = (const float*)d_in[3];
    const float* b1  = (const float*)d_in[4];
    const float* m1  = (const float*)d_in[5];
    const float* v1  = (const float*)d_in[6];
    const float* pw  = (const float*)d_in[7];
    const float* pb  = (const float*)d_in[8];
    const float* g2  = (const float*)d_in[9];
    const float* b2  = (const float*)d_in[10];
    const float* m2  = (const float*)d_in[11];
    const float* v2  = (const float*)d_in[12];
    float* out = (float*)d_out;

    static int smem_set = 0;
    if (!smem_set) {
        cudaFuncSetAttribute(dwsep3d_mma_kernel,
                             cudaFuncAttributeMaxDynamicSharedMemorySize,
                             SM_TOTAL);
        smem_set = 1;
    }

    dim3 grid(NB * ND * 24);   // 2304 blocks: one (b,d,h-pair) -> 96 voxels
    dim3 block(256);
    dwsep3d_mma_kernel<<<grid, block, SM_TOTAL>>>(x, dwk, dwb, g1, b1, m1, v1,
                                                  pw, pb, g2, b2, m2, v2, out);
}